// round 11
// baseline (speedup 1.0000x reference)
#include <cuda_runtime.h>
#include <cstdint>

// Problem constants
#define BB   8
#define C    256
#define HH   64
#define WW   64
#define K2   9
#define COUT 256
#define PLANE (HH*WW)      // 4096
#define NPIX  (BB*PLANE)   // 32768
#define KJ   2304          // C*K2

// ---------------------------------------------------------------------------
// Static device scratch
// ---------------------------------------------------------------------------
__device__ float g_mw0[BB*K2*PLANE];
__device__ float g_mw1[BB*K2*PLANE];
__device__ float g_mw2[BB*K2*PLANE];
__device__ float g_mw3[BB*K2*PLANE];
__device__ int   g_mi0[BB*K2*PLANE];
__device__ int   g_mi1[BB*K2*PLANE];
__device__ int   g_mi2[BB*K2*PLANE];
__device__ int   g_mi3[BB*K2*PLANE];

// Weights bf16, 2 planes: [plane][o][j]  (plane0=hi, plane1=lo), j = k9*256+c
__device__ __align__(16) unsigned short g_A[2 * COUT * KJ];

// x transposed to NHWC: g_xt[((b*4096 + pix) * 256) + c]
__device__ __align__(16) float g_xt[(size_t)NPIX * C];     // 134 MB

// ---------------------------------------------------------------------------
__device__ __forceinline__ void bsplit(float v, unsigned &h, unsigned &l) {
    unsigned u = __float_as_uint(v);
    unsigned r = (u + 0x7FFFu + ((u >> 16) & 1u)) & 0xFFFF0000u;
    h = r >> 16;
    float d = v - __uint_as_float(r);
    unsigned ud = __float_as_uint(d);
    l = (ud + 0x7FFFu + ((ud >> 16) & 1u)) >> 16;
}

// ---------------------------------------------------------------------------
// Kernel 1: weight prep
// ---------------------------------------------------------------------------
__global__ void aprep_kernel(const float* __restrict__ w) {
    int idx = blockIdx.x * 256 + threadIdx.x;
    if (idx >= COUT * KJ) return;
    int o = idx / KJ;
    int j = idx - o * KJ;
    int c = j & 255, k9 = j >> 8;
    float v = w[((o << 8) + c) * 9 + k9];
    unsigned h, l; bsplit(v, h, l);
    g_A[idx]             = (unsigned short)h;
    g_A[COUT*KJ + idx]   = (unsigned short)l;
}

// ---------------------------------------------------------------------------
// Kernel 2: bilinear metadata
// ---------------------------------------------------------------------------
__global__ void meta_kernel(const float* __restrict__ off) {
    int e = blockIdx.x * 256 + threadIdx.x;
    if (e >= BB*K2*PLANE) return;
    int p  = e & (PLANE - 1);
    int bk = e >> 12;
    int k  = bk % 9;
    int b  = bk / 9;
    int ho = p >> 6;
    int wo = p & 63;

    float dy = off[((size_t)(b*18 + 2*k    ) << 12) + p];
    float dx = off[((size_t)(b*18 + 2*k + 1) << 12) + p];

    float py = (float)(ho - 1 + (k / 3)) + dy;
    float px = (float)(wo - 1 + (k % 3)) + dx;

    float y0f = floorf(py), x0f = floorf(px);
    float fy = py - y0f, fx = px - x0f;
    int   y0 = (int)y0f,  x0 = (int)x0f;

    float wy[2] = {1.0f - fy, fy};
    float wx[2] = {1.0f - fx, fx};
    int   ys[2] = {y0, y0 + 1};
    int   xs[2] = {x0, x0 + 1};

    float mw[4]; int mi[4];
    #pragma unroll
    for (int jy = 0; jy < 2; jy++)
        #pragma unroll
        for (int jx = 0; jx < 2; jx++) {
            int jj = jy*2 + jx;
            int cy = ys[jy], cx = xs[jx];
            bool valid = (cy >= 0) && (cy < HH) && (cx >= 0) && (cx < WW);
            float wgt = valid ? wy[jy] * wx[jx] : 0.0f;
            int iy = min(max(cy, 0), HH - 1);
            int ix = min(max(cx, 0), WW - 1);
            mw[jj] = wgt;
            mi[jj] = iy * WW + ix;
        }
    g_mw0[e] = mw[0]; g_mw1[e] = mw[1]; g_mw2[e] = mw[2]; g_mw3[e] = mw[3];
    g_mi0[e] = mi[0]; g_mi1[e] = mi[1]; g_mi2[e] = mi[2]; g_mi3[e] = mi[3];
}

// ---------------------------------------------------------------------------
// Kernel 3: NCHW -> NHWC transpose (32x32 tiles via smem)
// ---------------------------------------------------------------------------
__global__ __launch_bounds__(256)
void xt_kernel(const float* __restrict__ x) {
    __shared__ float ts[32][33];
    int bid = blockIdx.x;
    int ct = (bid & 7) << 5;
    int pt = ((bid >> 3) & 127) << 5;
    int b  = bid >> 10;
    int l0 = threadIdx.x & 31;
    int l1 = threadIdx.x >> 5;
    const float* xb = x + ((size_t)b << 20);
    #pragma unroll
    for (int r = 0; r < 4; r++) {
        int c = ct + l1 + r * 8;
        ts[l1 + r * 8][l0] = xb[((size_t)c << 12) + pt + l0];
    }
    __syncthreads();
    float* xo = g_xt + (((size_t)(b << 12) + pt) << 8) + ct;
    #pragma unroll
    for (int r = 0; r < 4; r++) {
        int p = l1 + r * 8;
        xo[((size_t)p << 8) + l0] = ts[l0][p];
    }
}

// ---------------------------------------------------------------------------
// Kernel 4: fused warp-specialized GEMM, 2 CTAs/SM
//   CTA: M=128 (Cout half) x N=64 pixels. 320 threads:
//     warps 0-7: MMA consumers (4Mx2N, warp tile 32x32, acc=32 regs)
//     warps 8-9: producers (cp.async A + NHWC gather B)
//   36 stages of BK=64. smem: A 2x32KB | B 2x16KB = 96KB -> 2 CTAs/SM.
//   Consumer uses B-fragment ping-pong across ks to hide LDSM latency.
// ---------------------------------------------------------------------------
#define SWZ(x) ((x) ^ (((x) >> 3) & 0x70))
#define NST2   36
#define SM_TOTAL 98304

static __device__ __forceinline__ uint32_t smem_u32(const void* p) {
    uint32_t a;
    asm("{ .reg .u64 t; cvta.to.shared.u64 t, %1; cvt.u32.u64 %0, t; }"
        : "=r"(a) : "l"(p));
    return a;
}
static __device__ __forceinline__ void cp16(uint32_t dst, const void* src) {
    asm volatile("cp.async.cg.shared.global [%0], [%1], 16;\n"
                 :: "r"(dst), "l"(src));
}
#define LDSM4(r0, r1, r2, r3, a)                                              \
    asm volatile("ldmatrix.sync.aligned.m8n8.x4.shared.b16 {%0,%1,%2,%3}, [%4];" \
                 : "=r"(r0), "=r"(r1), "=r"(r2), "=r"(r3) : "r"(a))
#define MMA16816(d, a0, a1, a2, a3, b0, b1)                                   \
    asm volatile("mma.sync.aligned.m16n8k16.row.col.f32.bf16.bf16.f32 "       \
                 "{%0,%1,%2,%3}, {%4,%5,%6,%7}, {%8,%9}, {%0,%1,%2,%3};"      \
                 : "+f"((d)[0]), "+f"((d)[1]), "+f"((d)[2]), "+f"((d)[3])     \
                 : "r"(a0), "r"(a1), "r"(a2), "r"(a3), "r"(b0), "r"(b1))
#define STS64(a, v0, v1)                                                      \
    asm volatile("st.shared.v2.b32 [%0], {%1,%2};"                            \
                 :: "r"(a), "r"(v0), "r"(v1) : "memory")
#define BAR_SYNC(id)   asm volatile("bar.sync %0, 320;"   :: "r"(id) : "memory")
#define BAR_ARRIVE(id) asm volatile("bar.arrive %0, 320;" :: "r"(id) : "memory")

// Producer: build stage sn into slot sn&1
static __device__ __forceinline__ void produceP(int sn, int t2, uint32_t sb,
                                                int b, int pin, int om0) {
    // ---- A (hi+lo, 32 KB) via cp.async: 2048 cp16 / 64 threads ----
    {
        uint32_t dst0 = sb + (sn & 1) * 32768;
        #pragma unroll
        for (int i = 0; i < 32; i++) {
            int id = t2 + (i << 6);          // 0..2047
            int pl = id >> 10;
            int idp = id & 1023;
            int row = idp >> 3;
            int kb = (idp & 7) << 4;
            const char* src = (const char*)g_A +
                (((size_t)(pl * COUT + om0 + row) * KJ + sn * 64) << 1) + kb;
            cp16(dst0 + pl * 16384 + SWZ(row * 128 + kb), src);
        }
        asm volatile("cp.async.commit_group;" ::: "memory");
    }
    // ---- B gather from NHWC, coalesced: 16 lanes per 256B channel row ----
    int k9 = sn >> 2, cb = (sn & 3) << 6;
    int pw = t2 >> 5, lane = t2 & 31;
    int phalf = lane >> 4, lane4 = lane & 15;
    uint32_t sBh = sb + 65536 + (sn & 1) * 16384;
    uint32_t sBl = sBh + 8192;
    const float* xb = g_xt + (((size_t)(b << 12)) << 8) + cb + (lane4 << 2);

    #pragma unroll
    for (int it = 0; it < 16; it++) {
        int px = (it << 2) + (pw << 1) + phalf;          // 0..63
        int e = ((b * 9 + k9) << 12) + pin + px;
        float w0 = g_mw0[e], w1 = g_mw1[e], w2 = g_mw2[e], w3 = g_mw3[e];
        int   i0 = g_mi0[e], i1 = g_mi1[e], i2 = g_mi2[e], i3 = g_mi3[e];
        float4 f0 = *(const float4*)(xb + ((size_t)i0 << 8));
        float4 f1 = *(const float4*)(xb + ((size_t)i1 << 8));
        float4 f2 = *(const float4*)(xb + ((size_t)i2 << 8));
        float4 f3 = *(const float4*)(xb + ((size_t)i3 << 8));
        float v0 = w0*f0.x + w1*f1.x + w2*f2.x + w3*f3.x;
        float v1 = w0*f0.y + w1*f1.y + w2*f2.y + w3*f3.y;
        float v2 = w0*f0.z + w1*f1.z + w2*f2.z + w3*f3.z;
        float v3 = w0*f0.w + w1*f1.w + w2*f2.w + w3*f3.w;
        unsigned u0 = __float_as_uint(v0), u1 = __float_as_uint(v1);
        unsigned u2 = __float_as_uint(v2), u3 = __float_as_uint(v3);
        float e0 = v0 - __uint_as_float(u0 & 0xFFFF0000u);
        float e1 = v1 - __uint_as_float(u1 & 0xFFFF0000u);
        float e2 = v2 - __uint_as_float(u2 & 0xFFFF0000u);
        float e3 = v3 - __uint_as_float(u3 & 0xFFFF0000u);
        unsigned h01 = __byte_perm(u0, u1, 0x7632);
        unsigned h23 = __byte_perm(u2, u3, 0x7632);
        unsigned l01 = __byte_perm(__float_as_uint(e0), __float_as_uint(e1), 0x7632);
        unsigned l23 = __byte_perm(__float_as_uint(e2), __float_as_uint(e3), 0x7632);
        int boff = (px << 7) + (lane4 << 3);
        STS64(sBh + SWZ(boff), h01, h23);
        STS64(sBl + SWZ(boff), l01, l23);
    }
    asm volatile("cp.async.wait_group 0;" ::: "memory");
}

__global__ __launch_bounds__(320, 2)
void dconv_fused(float* __restrict__ out) {
    extern __shared__ char smem[];
    uint32_t sb = smem_u32(smem);
    int tid = threadIdx.x;
    int wid = tid >> 5, lid = tid & 31;
    const int gp0 = blockIdx.x << 6;             // global pixel base (64 px)
    const int b = gp0 >> 12;
    const int pin = gp0 & 4095;
    const int om0 = blockIdx.y << 7;             // Cout half base

    if (tid >= 256) {
        // ---------------- producer warps ----------------
        int t2 = tid - 256;
        for (int sn = 0; sn < NST2; sn++) {
            if (sn >= 2) BAR_SYNC(1);
            produceP(sn, t2, sb, b, pin, om0);
            BAR_ARRIVE(0);
        }
        return;
    }

    // ---------------- consumer warps ----------------
    const int wm0 = (wid & 3) << 5;              // 0/32/64/96
    const int wn0 = (wid >> 2) << 5;             // 0/32
    float acc[2][4][4];
    #pragma unroll
    for (int i = 0; i < 2; i++)
        #pragma unroll
        for (int j = 0; j < 4; j++)
            #pragma unroll
            for (int r = 0; r < 4; r++) acc[i][j][r] = 0.0f;

    int lr = lid & 15, lc = (lid >> 4) << 4;

    for (int s = 0; s < NST2; s++) {
        BAR_SYNC(0);
        uint32_t base = sb + (s & 1) * 32768;
        uint32_t sAh = base, sAl = base + 16384;
        uint32_t sBh = sb + 65536 + (s & 1) * 16384;
        uint32_t sBl = sBh + 8192;

        uint32_t bh[2][2][4], bl[2][2][4];       // [set][bt][reg]
        // preload B frags for ks=0 into set 0
        #pragma unroll
        for (int bt = 0; bt < 2; bt++) {
            uint32_t bd = sBh + SWZ((wn0 + (bt << 4) + lr) * 128 + lc);
            LDSM4(bh[0][bt][0], bh[0][bt][1], bh[0][bt][2], bh[0][bt][3], bd);
            uint32_t bd2 = sBl + SWZ((wn0 + (bt << 4) + lr) * 128 + lc);
            LDSM4(bl[0][bt][0], bl[0][bt][1], bl[0][bt][2], bl[0][bt][3], bd2);
        }

        #pragma unroll
        for (int ks = 0; ks < 4; ks++) {
            int cur = ks & 1, nxt = cur ^ 1;
            int kb = ks << 5;
            // prefetch B frags for ks+1 (hidden under this ks's MMAs)
            if (ks < 3) {
                int kb2 = (ks + 1) << 5;
                #pragma unroll
                for (int bt = 0; bt < 2; bt++) {
                    uint32_t bd = sBh + SWZ((wn0 + (bt << 4) + lr) * 128 + kb2 + lc);
                    LDSM4(bh[nxt][bt][0], bh[nxt][bt][1], bh[nxt][bt][2], bh[nxt][bt][3], bd);
                    uint32_t bd2 = sBl + SWZ((wn0 + (bt << 4) + lr) * 128 + kb2 + lc);
                    LDSM4(bl[nxt][bt][0], bl[nxt][bt][1], bl[nxt][bt][2], bl[nxt][bt][3], bd2);
                }
            }
            // A-hi fragments, then 32 MMAs
            uint32_t af[2][4];
            #pragma unroll
            for (int mt = 0; mt < 2; mt++) {
                uint32_t ad = sAh + SWZ((wm0 + (mt << 4) + lr) * 128 + kb + lc);
                LDSM4(af[mt][0], af[mt][1], af[mt][2], af[mt][3], ad);
            }
            #pragma unroll
            for (int mt = 0; mt < 2; mt++)
                #pragma unroll
                for (int n8 = 0; n8 < 4; n8++) {
                    int bt = n8 >> 1, nn = n8 & 1;
                    MMA16816(acc[mt][n8], af[mt][0], af[mt][1], af[mt][2], af[mt][3],
                             bh[cur][bt][nn], bh[cur][bt][nn + 2]);
                }
            #pragma unroll
            for (int mt = 0; mt < 2; mt++)
                #pragma unroll
                for (int n8 = 0; n8 < 4; n8++) {
                    int bt = n8 >> 1, nn = n8 & 1;
                    MMA16816(acc[mt][n8], af[mt][0], af[mt][1], af[mt][2], af[mt][3],
                             bl[cur][bt][nn], bl[cur][bt][nn + 2]);
                }
            // A-lo fragments x B-hi
            #pragma unroll
            for (int mt = 0; mt < 2; mt++) {
                uint32_t ad = sAl + SWZ((wm0 + (mt << 4) + lr) * 128 + kb + lc);
                LDSM4(af[mt][0], af[mt][1], af[mt][2], af[mt][3], ad);
            }
            #pragma unroll
            for (int mt = 0; mt < 2; mt++)
                #pragma unroll
                for (int n8 = 0; n8 < 4; n8++) {
                    int bt = n8 >> 1, nn = n8 & 1;
                    MMA16816(acc[mt][n8], af[mt][0], af[mt][1], af[mt][2], af[mt][3],
                             bh[cur][bt][nn], bh[cur][bt][nn + 2]);
                }
        }
        if (s + 2 < NST2) BAR_ARRIVE(1);
    }

    // epilogue: out[((b*256 + o) << 12) + pin + col]
    #pragma unroll
    for (int mt = 0; mt < 2; mt++) {
        int o = om0 + wm0 + (mt << 4) + (lid >> 2);
        float* rp = out + (((size_t)((b << 8) + o)) << 12) + pin;
        #pragma unroll
        for (int n8 = 0; n8 < 4; n8++) {
            int col = wn0 + (n8 << 3) + ((lid & 3) << 1);
            *(float2*)(rp + col)             = make_float2(acc[mt][n8][0], acc[mt][n8][1]);
            *(float2*)(rp + (8 << 12) + col) = make_float2(acc[mt][n8][2], acc[mt][n8][3]);
        }
    }
}

// ---------------------------------------------------------------------------
extern "C" void kernel_launch(void* const* d_in, const int* in_sizes, int n_in,
                              void* d_out, int out_size) {
    const float* x   = (const float*)d_in[0];
    const float* off = (const float*)d_in[1];
    const float* w   = (const float*)d_in[2];
    float* out = (float*)d_out;

    cudaFuncSetAttribute(dconv_fused,
                         cudaFuncAttributeMaxDynamicSharedMemorySize, SM_TOTAL);

    aprep_kernel<<<(COUT*KJ + 255) / 256, 256>>>(w);
    meta_kernel<<<(BB*K2*PLANE + 255) / 256, 256>>>(off);
    xt_kernel<<<BB * 128 * 8, 256>>>(x);

    dim3 grid(NPIX / 64, 2);
    dconv_fused<<<grid, 320, SM_TOTAL>>>(out);
}

// round 15
// speedup vs baseline: 1.4116x; 1.4116x over previous
#include <cuda_runtime.h>
#include <cuda_fp16.h>
#include <cstdint>

// Problem constants
#define BB   8
#define C    256
#define HH   64
#define WW   64
#define K2   9
#define COUT 256
#define PLANE (HH*WW)      // 4096
#define NPIX  (BB*PLANE)   // 32768
#define KJ   2304          // C*K2

// ---------------------------------------------------------------------------
// Static device scratch
// ---------------------------------------------------------------------------
__device__ float g_mw0[BB*K2*PLANE];
__device__ float g_mw1[BB*K2*PLANE];
__device__ float g_mw2[BB*K2*PLANE];
__device__ float g_mw3[BB*K2*PLANE];
__device__ int   g_mi0[BB*K2*PLANE];
__device__ int   g_mi1[BB*K2*PLANE];
__device__ int   g_mi2[BB*K2*PLANE];
__device__ int   g_mi3[BB*K2*PLANE];

// Weights fp16, single plane: [o][j], j = k9*256 + c
__device__ __align__(16) unsigned short g_A[COUT * KJ];

// x transposed to NHWC: g_xt[((b*4096 + pix) * 256) + c]
__device__ __align__(16) float g_xt[(size_t)NPIX * C];     // 134 MB

// ---------------------------------------------------------------------------
// Kernel 1: weight prep (fp32 -> fp16 RNE)
// ---------------------------------------------------------------------------
__global__ void aprep_kernel(const float* __restrict__ w) {
    int idx = blockIdx.x * 256 + threadIdx.x;
    if (idx >= COUT * KJ) return;
    int o = idx / KJ;
    int j = idx - o * KJ;
    int c = j & 255, k9 = j >> 8;
    float v = w[((o << 8) + c) * 9 + k9];
    __half h = __float2half_rn(v);
    g_A[idx] = *(unsigned short*)&h;
}

// ---------------------------------------------------------------------------
// Kernel 2: bilinear metadata
// ---------------------------------------------------------------------------
__global__ void meta_kernel(const float* __restrict__ off) {
    int e = blockIdx.x * 256 + threadIdx.x;
    if (e >= BB*K2*PLANE) return;
    int p  = e & (PLANE - 1);
    int bk = e >> 12;
    int k  = bk % 9;
    int b  = bk / 9;
    int ho = p >> 6;
    int wo = p & 63;

    float dy = off[((size_t)(b*18 + 2*k    ) << 12) + p];
    float dx = off[((size_t)(b*18 + 2*k + 1) << 12) + p];

    float py = (float)(ho - 1 + (k / 3)) + dy;
    float px = (float)(wo - 1 + (k % 3)) + dx;

    float y0f = floorf(py), x0f = floorf(px);
    float fy = py - y0f, fx = px - x0f;
    int   y0 = (int)y0f,  x0 = (int)x0f;

    float wy[2] = {1.0f - fy, fy};
    float wx[2] = {1.0f - fx, fx};
    int   ys[2] = {y0, y0 + 1};
    int   xs[2] = {x0, x0 + 1};

    float mw[4]; int mi[4];
    #pragma unroll
    for (int jy = 0; jy < 2; jy++)
        #pragma unroll
        for (int jx = 0; jx < 2; jx++) {
            int jj = jy*2 + jx;
            int cy = ys[jy], cx = xs[jx];
            bool valid = (cy >= 0) && (cy < HH) && (cx >= 0) && (cx < WW);
            float wgt = valid ? wy[jy] * wx[jx] : 0.0f;
            int iy = min(max(cy, 0), HH - 1);
            int ix = min(max(cx, 0), WW - 1);
            mw[jj] = wgt;
            mi[jj] = iy * WW + ix;
        }
    g_mw0[e] = mw[0]; g_mw1[e] = mw[1]; g_mw2[e] = mw[2]; g_mw3[e] = mw[3];
    g_mi0[e] = mi[0]; g_mi1[e] = mi[1]; g_mi2[e] = mi[2]; g_mi3[e] = mi[3];
}

// ---------------------------------------------------------------------------
// Kernel 3: NCHW -> NHWC transpose (32x32 tiles via smem)
// ---------------------------------------------------------------------------
__global__ __launch_bounds__(256)
void xt_kernel(const float* __restrict__ x) {
    __shared__ float ts[32][33];
    int bid = blockIdx.x;
    int ct = (bid & 7) << 5;
    int pt = ((bid >> 3) & 127) << 5;
    int b  = bid >> 10;
    int l0 = threadIdx.x & 31;
    int l1 = threadIdx.x >> 5;
    const float* xb = x + ((size_t)b << 20);
    #pragma unroll
    for (int r = 0; r < 4; r++) {
        int c = ct + l1 + r * 8;
        ts[l1 + r * 8][l0] = xb[((size_t)c << 12) + pt + l0];
    }
    __syncthreads();
    float* xo = g_xt + (((size_t)(b << 12) + pt) << 8) + ct;
    #pragma unroll
    for (int r = 0; r < 4; r++) {
        int p = l1 + r * 8;
        xo[((size_t)p << 8) + l0] = ts[l0][p];
    }
}

// ---------------------------------------------------------------------------
// Kernel 4: fused warp-specialized single-pass fp16 GEMM
//   CTA: M=256 x N=128 pixels. 640 threads:
//     warps 0-15: MMA consumers (4Mx4N, warp tile 64x32)
//     warps 16-19: producers (cp.async A + NHWC gather B)
//   36 stages of BK=64. smem: A 2x32KB | B 2x16KB = 96KB.
//   barrier 0: tile-ready; barrier 1: tile-consumed.
// ---------------------------------------------------------------------------
#define SWZ(x) ((x) ^ (((x) >> 3) & 0x70))
#define NST2   36
#define SM_TOTAL 98304

static __device__ __forceinline__ uint32_t smem_u32(const void* p) {
    uint32_t a;
    asm("{ .reg .u64 t; cvta.to.shared.u64 t, %1; cvt.u32.u64 %0, t; }"
        : "=r"(a) : "l"(p));
    return a;
}
static __device__ __forceinline__ void cp16(uint32_t dst, const void* src) {
    asm volatile("cp.async.cg.shared.global [%0], [%1], 16;\n"
                 :: "r"(dst), "l"(src));
}
#define LDSM4(r0, r1, r2, r3, a)                                              \
    asm volatile("ldmatrix.sync.aligned.m8n8.x4.shared.b16 {%0,%1,%2,%3}, [%4];" \
                 : "=r"(r0), "=r"(r1), "=r"(r2), "=r"(r3) : "r"(a))
#define MMAF16(d, a0, a1, a2, a3, b0, b1)                                     \
    asm volatile("mma.sync.aligned.m16n8k16.row.col.f32.f16.f16.f32 "         \
                 "{%0,%1,%2,%3}, {%4,%5,%6,%7}, {%8,%9}, {%0,%1,%2,%3};"      \
                 : "+f"((d)[0]), "+f"((d)[1]), "+f"((d)[2]), "+f"((d)[3])     \
                 : "r"(a0), "r"(a1), "r"(a2), "r"(a3), "r"(b0), "r"(b1))
#define STS64(a, v0, v1)                                                      \
    asm volatile("st.shared.v2.b32 [%0], {%1,%2};"                            \
                 :: "r"(a), "r"(v0), "r"(v1) : "memory")
#define BAR_SYNC(id)   asm volatile("bar.sync %0, 640;"   :: "r"(id) : "memory")
#define BAR_ARRIVE(id) asm volatile("bar.arrive %0, 640;" :: "r"(id) : "memory")
// pack two fp32 -> fp16x2 (lo = second source)
#define F16X2(dst, vlo, vhi)                                                  \
    asm("cvt.rn.f16x2.f32 %0, %1, %2;" : "=r"(dst) : "f"(vhi), "f"(vlo))

// Producer: build stage sn into slot sn&1
static __device__ __forceinline__ void produceP(int sn, int t2, uint32_t sb,
                                                int b, int pin) {
    // ---- A (fp16, 32 KB) via cp.async: 2048 cp16 / 128 threads ----
    {
        uint32_t dst0 = sb + (sn & 1) * 32768;
        #pragma unroll
        for (int i = 0; i < 16; i++) {
            int id = t2 + (i << 7);          // 0..2047
            int row = id >> 3;               // 0..255
            int kb = (id & 7) << 4;
            const char* src = (const char*)g_A +
                (((size_t)row * KJ + sn * 64) << 1) + kb;
            cp16(dst0 + SWZ(row * 128 + kb), src);
        }
        asm volatile("cp.async.commit_group;" ::: "memory");
    }
    // ---- B gather from NHWC (fp32 math, fp16 pack), coalesced ----
    int k9 = sn >> 2, cb = (sn & 3) << 6;
    int pw = t2 >> 5, lane = t2 & 31;
    int phalf = lane >> 4, lane4 = lane & 15;
    uint32_t sB = sb + 65536 + (sn & 1) * 16384;
    const float* xb = g_xt + (((size_t)(b << 12)) << 8) + cb + (lane4 << 2);

    #pragma unroll
    for (int it = 0; it < 16; it++) {
        int px = (it << 3) + (pw << 1) + phalf;          // 0..127
        int e = ((b * 9 + k9) << 12) + pin + px;
        float w0 = g_mw0[e], w1 = g_mw1[e], w2 = g_mw2[e], w3 = g_mw3[e];
        int   i0 = g_mi0[e], i1 = g_mi1[e], i2 = g_mi2[e], i3 = g_mi3[e];
        float4 f0 = *(const float4*)(xb + ((size_t)i0 << 8));
        float4 f1 = *(const float4*)(xb + ((size_t)i1 << 8));
        float4 f2 = *(const float4*)(xb + ((size_t)i2 << 8));
        float4 f3 = *(const float4*)(xb + ((size_t)i3 << 8));
        float v0 = w0*f0.x + w1*f1.x + w2*f2.x + w3*f3.x;
        float v1 = w0*f0.y + w1*f1.y + w2*f2.y + w3*f3.y;
        float v2 = w0*f0.z + w1*f1.z + w2*f2.z + w3*f3.z;
        float v3 = w0*f0.w + w1*f1.w + w2*f2.w + w3*f3.w;
        unsigned h01, h23;
        F16X2(h01, v0, v1);
        F16X2(h23, v2, v3);
        int boff = (px << 7) + (lane4 << 3);
        STS64(sB + SWZ(boff), h01, h23);
    }
    asm volatile("cp.async.wait_group 0;" ::: "memory");
}

__global__ __launch_bounds__(640, 1)
void dconv_fused(float* __restrict__ out) {
    extern __shared__ char smem[];
    uint32_t sb = smem_u32(smem);
    int tid = threadIdx.x;
    int wid = tid >> 5, lid = tid & 31;
    const int pt0 = blockIdx.x << 7;
    const int b = pt0 >> 12;
    const int pin = pt0 & 4095;

    if (tid >= 512) {
        // ---------------- producer warps ----------------
        int t2 = tid - 512;
        for (int sn = 0; sn < NST2; sn++) {
            if (sn >= 2) BAR_SYNC(1);
            produceP(sn, t2, sb, b, pin);
            BAR_ARRIVE(0);
        }
        return;
    }

    // ---------------- consumer warps ----------------
    const int wm0 = (wid & 3) << 6;
    const int wn0 = (wid >> 2) << 5;
    float acc[4][4][4];
    #pragma unroll
    for (int i = 0; i < 4; i++)
        #pragma unroll
        for (int j = 0; j < 4; j++)
            #pragma unroll
            for (int r = 0; r < 4; r++) acc[i][j][r] = 0.0f;

    int lr = lid & 15, lc = (lid >> 4) << 4;

    for (int s = 0; s < NST2; s++) {
        BAR_SYNC(0);
        uint32_t sA = sb + (s & 1) * 32768;
        uint32_t sB = sb + 65536 + (s & 1) * 16384;

        #pragma unroll
        for (int ks = 0; ks < 4; ks++) {
            int kb = ks << 5;
            uint32_t bh[2][4];
            #pragma unroll
            for (int bt = 0; bt < 2; bt++) {
                uint32_t bd = sB + SWZ((wn0 + (bt << 4) + lr) * 128 + kb + lc);
                LDSM4(bh[bt][0], bh[bt][1], bh[bt][2], bh[bt][3], bd);
            }
            #pragma unroll
            for (int mt = 0; mt < 4; mt++) {
                uint32_t a0, a1, a2, a3;
                uint32_t ad = sA + SWZ((wm0 + (mt << 4) + lr) * 128 + kb + lc);
                LDSM4(a0, a1, a2, a3, ad);
                #pragma unroll
                for (int n8 = 0; n8 < 4; n8++) {
                    int bt = n8 >> 1, nn = n8 & 1;
                    MMAF16(acc[mt][n8], a0, a1, a2, a3, bh[bt][nn], bh[bt][nn + 2]);
                }
            }
        }
        if (s + 2 < NST2) BAR_ARRIVE(1);
    }

    // epilogue
    #pragma unroll
    for (int mt = 0; mt < 4; mt++) {
        int o = wm0 + (mt << 4) + (lid >> 2);
        float* rp = out + (((size_t)((b << 8) + o)) << 12) + pin;
        #pragma unroll
        for (int n8 = 0; n8 < 4; n8++) {
            int col = wn0 + (n8 << 3) + ((lid & 3) << 1);
            *(float2*)(rp + col)             = make_float2(acc[mt][n8][0], acc[mt][n8][1]);
            *(float2*)(rp + (8 << 12) + col) = make_float2(acc[mt][n8][2], acc[mt][n8][3]);
        }
    }
}

// ---------------------------------------------------------------------------
extern "C" void kernel_launch(void* const* d_in, const int* in_sizes, int n_in,
                              void* d_out, int out_size) {
    const float* x   = (const float*)d_in[0];
    const float* off = (const float*)d_in[1];
    const float* w   = (const float*)d_in[2];
    float* out = (float*)d_out;

    cudaFuncSetAttribute(dconv_fused,
                         cudaFuncAttributeMaxDynamicSharedMemorySize, SM_TOTAL);

    aprep_kernel<<<(COUT*KJ + 255) / 256, 256>>>(w);
    meta_kernel<<<(BB*K2*PLANE + 255) / 256, 256>>>(off);
    xt_kernel<<<BB * 128 * 8, 256>>>(x);

    dconv_fused<<<NPIX / 128, 640, SM_TOTAL>>>(out);
}